// round 10
// baseline (speedup 1.0000x reference)
#include <cuda_runtime.h>
#include <cstdint>
#include <cstddef>
#include <vector>
#include <algorithm>

#define DIMS 256
#define N_ITERS 100
#define RPT 64                  // rows per tile
#define PITCH4 65               // float4 per row (64 data + 1 pad)
#define TILE4 (RPT * PITCH4)    // 4160 float4 = 66,560 B
#define NB 148
#define TPB 256
#define RES_TILES 1526          // ~100 MB marked L2 evict_last

// ---------------- device state ----------------
__device__ __align__(16) float g_c[2][DIMS];
__device__ float  g_q[2];
__device__ double g_sum1[DIMS];
__device__ double g_tot[DIMS];
__device__ unsigned long long g_cnt1;
__device__ float  g_xsq[262144];

// ---------------- x_sq: XLA row-reduce, float2 pattern (bit-exact, DO NOT TOUCH) ----
__global__ void xsq_kernel(const float* __restrict__ x, int n) {
    int row  = blockIdx.x * (blockDim.x >> 5) + (threadIdx.x >> 5);
    int lane = threadIdx.x & 31;
    if (row >= n) return;
    const float2* xr = (const float2*)(x + (size_t)row * DIMS);
    float acc = 0.f;
    #pragma unroll
    for (int j = 0; j < 4; j++) {
        float2 v = xr[lane + 32 * j];
        acc = __fadd_rn(acc, __fmul_rn(v.x, v.x));
        acc = __fadd_rn(acc, __fmul_rn(v.y, v.y));
    }
    #pragma unroll
    for (int o = 16; o > 0; o >>= 1)
        acc = __fadd_rn(acc, __shfl_xor_sync(0xffffffffu, acc, o));
    if (lane == 0) g_xsq[row] = acc;
}

__device__ __forceinline__ void q_from_centers(int d) {
    if (d < 64) {
        int w = d >> 5, lane = d & 31;
        const float2* cr = (const float2*)g_c[w];
        float acc = 0.f;
        #pragma unroll
        for (int j = 0; j < 4; j++) {
            float2 v = cr[lane + 32 * j];
            acc = __fadd_rn(acc, __fmul_rn(v.x, v.x));
            acc = __fadd_rn(acc, __fmul_rn(v.y, v.y));
        }
        #pragma unroll
        for (int o = 16; o > 0; o >>= 1)
            acc = __fadd_rn(acc, __shfl_xor_sync(0xffffffffu, acc, o));
        if (lane == 0) g_q[w] = acc;
    }
}

__global__ void init_kernel(const float* __restrict__ x, int i0, int i1) {
    int d = threadIdx.x;
    g_c[0][d] = x[(size_t)i0 * DIMS + d];
    g_c[1][d] = x[(size_t)i1 * DIMS + d];
    g_sum1[d] = 0.0;
    g_tot[d]  = 0.0;
    if (d == 0) g_cnt1 = 0ull;
    __syncthreads();
    q_from_centers(d);
}

// per-column double totals (once per launch; order-free)
__global__ void tot_kernel(const float* __restrict__ x, int n) {
    int c = threadIdx.x;
    double acc = 0.0;
    for (int r = blockIdx.x; r < n; r += gridDim.x)
        acc += (double)x[(size_t)r * DIMS + c];
    atomicAdd(&g_tot[c], acc);
}

// ---------------- warp-specialized 3-stage pipelined assign ----------------
// warps 0-1: dot (thread-per-row, bit-exact serial FMA)
// warps 2-3: cluster-1 column sums of previous tile
// all threads: cp.async issue of next tile
extern __shared__ float4 s4[];
__global__ __launch_bounds__(TPB, 1) void assign_kernel(const float* __restrict__ x, int n) {
    float4* c04 = s4 + 3 * TILE4;       // 64
    float4* c14 = c04 + 64;             // 64
    __shared__ unsigned smask[2][2];    // [stage parity][warp 0/1 rows]

    const int tid = threadIdx.x, lane = tid & 31, wid = tid >> 5;
    const int bid = blockIdx.x;

    for (int i = tid; i < 64; i += TPB) {
        c04[i] = ((const float4*)g_c[0])[i];
        c14[i] = ((const float4*)g_c[1])[i];
    }
    __syncthreads();
    const float q0 = g_q[0], q1 = g_q[1];
    const int ntiles = (n + RPT - 1) / RPT;     // 3125 (exact: 200000/64)

    uint32_t sbase = (uint32_t)__cvta_generic_to_shared(s4);
    uint64_t polKeep, polStream;
    asm volatile("createpolicy.fractional.L2::evict_last.b64 %0, 1.0;"  : "=l"(polKeep));
    asm volatile("createpolicy.fractional.L2::evict_first.b64 %0, 1.0;" : "=l"(polStream));

    double dX = 0, dY = 0, dZ = 0, dW = 0;      // sum-warp col accumulators
    unsigned long long myCnt = 0;               // dot-warp lane0 counts

    auto issue_tile = [&](int t, int b) {
        const float4* src = (const float4*)x + (size_t)t * (RPT * 64);
        const int lim = (min(RPT, n - t * RPT)) * 64;
        const uint64_t pol = (t < RES_TILES) ? polKeep : polStream;
        #pragma unroll
        for (int k = 0; k < 16; k++) {
            int e = tid + k * TPB;
            if (e < lim) {
                int r = e >> 6, j = e & 63;
                uint32_t dst = sbase + 16u * (unsigned)(b * TILE4 + r * PITCH4 + j);
                asm volatile("cp.async.cg.shared.global.L2::cache_hint [%0], [%1], 16, %2;"
                             :: "r"(dst), "l"(src + e), "l"(pol) : "memory");
            }
        }
    };

    // prologue: tile for stage 0 into buffer 0
    if (bid < ntiles) issue_tile(bid, 0);
    asm volatile("cp.async.commit_group;" ::: "memory");

    for (int s = 0;; s++) {
        const long tcur  = (long)bid + (long)s * NB;
        const long tprev = tcur - NB;
        if (tcur >= ntiles && tprev >= ntiles) break;

        __syncthreads();   // sum(tprev-1) readers done before overwriting buf[(s+1)%3]
        const long tnext = tcur + NB;
        if (tnext < ntiles) issue_tile((int)tnext, (int)((s + 1) % 3));
        asm volatile("cp.async.commit_group;" ::: "memory");
        asm volatile("cp.async.wait_group 1;" ::: "memory");
        __syncthreads();   // tile s visible to all

        if (tid < 64) {
            // ---- dot: bit-exact serial ascending-k FMA ----
            if (tcur < ntiles) {
                const int row = (int)tcur * RPT + tid;
                const float4* rp = s4 + (s % 3) * TILE4 + tid * PITCH4;
                float xsq = (row < n) ? __ldg(&g_xsq[row]) : 0.f;
                float s0 = 0.f, s1 = 0.f;
                #pragma unroll 16
                for (int j = 0; j < 64; j++) {
                    float4 v  = rp[j];
                    float4 c0 = c04[j];
                    float4 c1 = c14[j];
                    s0 = __fmaf_rn(v.x, c0.x, s0); s1 = __fmaf_rn(v.x, c1.x, s1);
                    s0 = __fmaf_rn(v.y, c0.y, s0); s1 = __fmaf_rn(v.y, c1.y, s1);
                    s0 = __fmaf_rn(v.z, c0.z, s0); s1 = __fmaf_rn(v.z, c1.z, s1);
                    s0 = __fmaf_rn(v.w, c0.w, s0); s1 = __fmaf_rn(v.w, c1.w, s1);
                }
                float d20 = __fadd_rn(__fsub_rn(xsq, __fmul_rn(2.0f, s0)), q0);
                float d21 = __fadd_rn(__fsub_rn(xsq, __fmul_rn(2.0f, s1)), q1);
                bool a1 = (row < n) && (d21 < d20);     // argmin, tie -> 0
                unsigned m = __ballot_sync(0xffffffffu, a1);
                if (lane == 0) { smask[s & 1][wid] = m; myCnt += (unsigned)__popc(m); }
            }
        } else if (tid < 128) {
            // ---- cluster-1 sums for previous tile ----
            if (tprev >= 0 && tprev < ntiles) {
                const int c4 = tid - 64;
                const float4* colp = s4 + ((s + 2) % 3) * TILE4 + c4;
                unsigned m0 = smask[(s + 1) & 1][0];
                unsigned m1 = smask[(s + 1) & 1][1];
                float aX = 0.f, aY = 0.f, aZ = 0.f, aW = 0.f;
                while (m0) {
                    int r = __ffs(m0) - 1; m0 &= m0 - 1;
                    float4 v = colp[r * PITCH4];
                    aX += v.x; aY += v.y; aZ += v.z; aW += v.w;
                }
                while (m1) {
                    int r = __ffs(m1) - 1; m1 &= m1 - 1;
                    float4 v = colp[(32 + r) * PITCH4];
                    aX += v.x; aY += v.y; aZ += v.z; aW += v.w;
                }
                dX += (double)aX; dY += (double)aY; dZ += (double)aZ; dW += (double)aW;
            }
        }
    }

    if (tid >= 64 && tid < 128) {
        const int c4 = tid - 64;
        atomicAdd(&g_sum1[4 * c4 + 0], dX);
        atomicAdd(&g_sum1[4 * c4 + 1], dY);
        atomicAdd(&g_sum1[4 * c4 + 2], dZ);
        atomicAdd(&g_sum1[4 * c4 + 3], dW);
    }
    if (tid < 64 && lane == 0) atomicAdd(&g_cnt1, myCnt);
}

__global__ void update_kernel(int n) {
    int d = threadIdx.x;
    unsigned long long c1n = g_cnt1;
    float cnt1f = (float)c1n;                              // exact (<2^24)
    float cnt0f = (float)(long long)((long long)n - (long long)c1n);
    double s1d = g_sum1[d];
    float  s1  = (float)s1d;
    float  s0  = (float)(g_tot[d] - s1d);
    float c0 = (cnt0f > 0.f) ? __fdiv_rn(s0, fmaxf(cnt0f, 1.f)) : g_c[0][d];
    float c1 = (cnt1f > 0.f) ? __fdiv_rn(s1, fmaxf(cnt1f, 1.f)) : g_c[1][d];
    __syncthreads();
    g_c[0][d] = c0; g_c[1][d] = c1;
    g_sum1[d] = 0.0;
    __syncthreads();
    q_from_centers(d);
    if (d == 0) g_cnt1 = 0ull;
}

__global__ void output_kernel(float* __restrict__ out, int n) {
    int d = threadIdx.x;
    unsigned long long c1n = g_cnt1;
    float mean = __fdiv_rn((float)c1n, (float)n);
    int maj = (mean > 0.5f) ? 1 : 0;
    float cm  = maj ? (float)c1n : (float)(long long)((long long)n - (long long)c1n);
    float cnt = fmaxf(cm, 1.0f);
    double s  = maj ? g_sum1[d] : (g_tot[d] - g_sum1[d]);
    out[d] = __fdiv_rn((float)s, cnt);
}

// ---------------- host: JAX threefry (partitionable/foldlike) init ----------------
static inline uint32_t rotl32(uint32_t v, int r) { return (v << r) | (v >> (32 - r)); }

static void tf2x32(uint32_t k0, uint32_t k1, uint32_t x0, uint32_t x1,
                   uint32_t* o0, uint32_t* o1) {
    uint32_t ks2 = k0 ^ k1 ^ 0x1BD11BDAu;
    x0 += k0; x1 += k1;
    static const int R0[4] = {13, 15, 26, 6};
    static const int R1[4] = {17, 29, 16, 24};
#define TF_RND(r) { x0 += x1; x1 = rotl32(x1, (r)); x1 ^= x0; }
    for (int i = 0; i < 4; i++) TF_RND(R0[i]);  x0 += k1;  x1 += ks2 + 1u;
    for (int i = 0; i < 4; i++) TF_RND(R1[i]);  x0 += ks2; x1 += k0 + 2u;
    for (int i = 0; i < 4; i++) TF_RND(R0[i]);  x0 += k0;  x1 += k1 + 3u;
    for (int i = 0; i < 4; i++) TF_RND(R1[i]);  x0 += k1;  x1 += ks2 + 4u;
    for (int i = 0; i < 4; i++) TF_RND(R0[i]);  x0 += ks2; x1 += k0 + 5u;
#undef TF_RND
    *o0 = x0; *o1 = x1;
}

static void init_indices(int n, int* pi0, int* pi1) {
    uint32_t K0, K1, S0, S1, T0, T1;
    tf2x32(0u, 42u, 0u, 0u, &K0, &K1);
    tf2x32(0u, 42u, 0u, 1u, &S0, &S1);
    tf2x32(K0, K1, 0u, 1u, &T0, &T1);

    std::vector<uint32_t> k1v((size_t)n), k2v((size_t)n);
    for (int i = 0; i < n; i++) {
        uint32_t a, b;
        tf2x32(S0, S1, 0u, (uint32_t)i, &a, &b); k1v[i] = a ^ b;
        tf2x32(T0, T1, 0u, (uint32_t)i, &a, &b); k2v[i] = a ^ b;
    }
    long q0 = -1, q1 = -1;
    for (int p = 0; p < n; p++) {
        uint32_t v = k2v[p];
        if (q0 < 0 || v < k2v[q0]) { q1 = q0; q0 = p; }
        else if (q1 < 0 || v < k2v[q1]) { q1 = p; }
    }
    std::vector<int> idx((size_t)n);
    for (int i = 0; i < n; i++) idx[i] = i;
    std::stable_sort(idx.begin(), idx.end(),
                     [&](int a, int b) { return k1v[a] < k1v[b]; });
    *pi0 = idx[q0];
    *pi1 = idx[q1];
}

// ---------------- entry ----------------
extern "C" void kernel_launch(void* const* d_in, const int* in_sizes, int n_in,
                              void* d_out, int out_size) {
    const float* x = (const float*)d_in[0];
    const int n = in_sizes[0] / DIMS;

    int i0 = 0, i1 = 1;
    init_indices(n, &i0, &i1);

    const int smem_bytes = (3 * TILE4 + 128) * 16;   // 201,728 B
    static bool attr_set = false;
    if (!attr_set) {
        cudaFuncSetAttribute(assign_kernel,
                             cudaFuncAttributeMaxDynamicSharedMemorySize, smem_bytes);
        attr_set = true;
    }

    init_kernel<<<1, DIMS>>>(x, i0, i1);
    xsq_kernel<<<(n + 7) / 8, 256>>>(x, n);
    tot_kernel<<<592, DIMS>>>(x, n);
    for (int t = 0; t < N_ITERS; t++) {
        assign_kernel<<<NB, TPB, smem_bytes>>>(x, n);
        if (t < N_ITERS - 1) update_kernel<<<1, DIMS>>>(n);
    }
    output_kernel<<<1, DIMS>>>((float*)d_out, n);
}